// round 11
// baseline (speedup 1.0000x reference)
#include <cuda_runtime.h>
#include <cuda_bf16.h>
#include <mma.h>
#include <cstdint>
#include <math.h>

using namespace nvcuda;

#define BB    8
#define TT    1024
#define HH    768
#define HD    384
#define GG    1536            // 4*HD gates per direction
#define SS    16
#define NBD   48              // blocks per direction in recurrence
#define GPB   32              // gate rows per block (GG/NBD)
#define CPB   8               // h columns per block

// ---------------- device scratch (no allocation allowed) ----------------
__device__ __align__(16) __nv_bfloat16 g_x_bf[(size_t)BB * TT * HH];        // layer input (bf16)
__device__ __align__(16) __nv_bfloat16 g_wbf[2][(size_t)2 * GG * HH];       // W_ih bf16 per layer (fwd rows then bwd rows)
__device__ __align__(16) float         g_gx[(size_t)BB * TT * 2 * GG];      // input projections [8192][3072]
__device__ __align__(16) float         g_enc[(size_t)BB * TT * HH];         // fp32 layer output
__device__ __align__(16) float         g_h[2 * 2 * BB * HD];                // [parity][dir][b*HD+k]
__device__ int                         g_ctr[4];                            // [layer*2+dir]

// ---------------- tiny kernels ----------------
__global__ void init_ctr_kernel() {
    if (threadIdx.x < 4) g_ctr[threadIdx.x] = 0;
}

__global__ void emb_kernel(const int* __restrict__ ids, const float* __restrict__ emb) {
    int row = blockIdx.x;                         // b*T + t
    int id  = ids[row];
    const float* src = emb + (size_t)id * HH;
    __nv_bfloat16* dst = g_x_bf + (size_t)row * HH;
    for (int i = threadIdx.x; i < HH; i += blockDim.x)
        dst[i] = __float2bfloat16_rn(src[i]);
}

__global__ void conv_w_kernel(const float* __restrict__ wf, const float* __restrict__ wb, int layer) {
    int i = blockIdx.x * blockDim.x + threadIdx.x;     // over 2*GG*HH = 2359296
    if (i < 2 * GG * HH) {
        float v = (i < GG * HH) ? wf[i] : wb[i - GG * HH];
        g_wbf[layer][i] = __float2bfloat16_rn(v);
    }
}

// ---------------- input-projection GEMM: gx[8192,3072] = X[8192,768] * W[3072,768]^T ----------------
// bf16 WMMA fp32 acc. Block tile 64x128, BK=32, 8 warps (2x4), warp tile 32x32.
__global__ __launch_bounds__(256) void gemm_bf16_kernel(const __nv_bfloat16* __restrict__ Bw) {
    __shared__ __align__(16) __nv_bfloat16 As[64][48];
    __shared__ __align__(16) __nv_bfloat16 Bs[128][48];

    const __nv_bfloat16* __restrict__ A = g_x_bf;
    float* __restrict__ C = g_gx;

    int tid = threadIdx.x;
    int m0 = blockIdx.y * 64;
    int n0 = blockIdx.x * 128;
    int warp = tid >> 5;
    int wm = warp >> 2, wn = warp & 3;      // 2 x 4 warps

    wmma::fragment<wmma::accumulator, 16, 16, 16, float> acc[2][2];
#pragma unroll
    for (int i = 0; i < 2; i++)
#pragma unroll
        for (int j = 0; j < 2; j++) wmma::fill_fragment(acc[i][j], 0.0f);

    for (int k0 = 0; k0 < HH; k0 += 32) {
        {
            int r = tid >> 2, c = (tid & 3) * 8;   // 64 rows x 32 k
            *(uint4*)&As[r][c] = *(const uint4*)&A[(size_t)(m0 + r) * HH + k0 + c];
        }
#pragma unroll
        for (int i = 0; i < 2; i++) {
            int idx = tid + i * 256;
            int r = idx >> 2, c = (idx & 3) * 8;   // 128 rows x 32 k
            *(uint4*)&Bs[r][c] = *(const uint4*)&Bw[(size_t)(n0 + r) * HH + k0 + c];
        }
        __syncthreads();
#pragma unroll
        for (int kf = 0; kf < 32; kf += 16) {
            wmma::fragment<wmma::matrix_a, 16, 16, 16, __nv_bfloat16, wmma::row_major> af[2];
            wmma::fragment<wmma::matrix_b, 16, 16, 16, __nv_bfloat16, wmma::col_major> bf[2];
            wmma::load_matrix_sync(af[0], &As[wm * 32][kf], 48);
            wmma::load_matrix_sync(af[1], &As[wm * 32 + 16][kf], 48);
            wmma::load_matrix_sync(bf[0], &Bs[wn * 32][kf], 48);
            wmma::load_matrix_sync(bf[1], &Bs[wn * 32 + 16][kf], 48);
#pragma unroll
            for (int i = 0; i < 2; i++)
#pragma unroll
                for (int j = 0; j < 2; j++)
                    wmma::mma_sync(acc[i][j], af[i], bf[j], acc[i][j]);
        }
        __syncthreads();
    }
#pragma unroll
    for (int i = 0; i < 2; i++)
#pragma unroll
        for (int j = 0; j < 2; j++)
            wmma::store_matrix_sync(&C[(size_t)(m0 + wm * 32 + i * 16) * (2 * GG) + n0 + wn * 32 + j * 16],
                                    acc[i][j], 2 * GG, wmma::mem_row_major);
}

// ---------------- recurrence: 96 persistent blocks (48/dir), per-step counter barrier --------------
// smem floats: w 12288 | h 3072 | part 2048 | gate 256 | bias 32 | c 64  = 17760 (71040 B)
#define RSMEM_FLOATS 17760
#define RSMEM_BYTES  (RSMEM_FLOATS * 4)

__global__ __launch_bounds__(256) void recur_kernel(
    int layer,
    const float* __restrict__ whh_f, const float* __restrict__ whh_b,
    const float* __restrict__ bih_f, const float* __restrict__ bhh_f,
    const float* __restrict__ bih_b, const float* __restrict__ bhh_b)
{
    extern __shared__ __align__(16) float sm[];
    float* w_sm    = sm;            // [kq 0..95][gl 0..31] float4
    float* h_sh    = sm + 12288;    // [b 0..7][kq 0..95] float4
    float* part    = sm + 15360;    // [warp][gl][b]
    float* gate_sh = sm + 17408;    // [gl][b]
    float* bias_sh = sm + 17664;    // [gl]
    float* c_sh    = sm + 17696;    // [c][b]

    int tid = threadIdx.x;
    int dir = blockIdx.x / NBD;             // 0 fwd, 1 bwd
    int bi  = blockIdx.x - dir * NBD;
    int col0 = bi * CPB;

    const float* whh = dir ? whh_b : whh_f;

    // stage W_hh slice: gl -> global gate row (gl>>3)*HD + col0 + (gl&7)
    for (int i = tid; i < GPB * HD; i += 256) {
        int gl = i / HD, k = i - gl * HD;
        int grow = (gl >> 3) * HD + col0 + (gl & 7);
        w_sm[(k >> 2) * 128 + gl * 4 + (k & 3)] = whh[(size_t)grow * HD + k];
    }
    if (tid < GPB) {
        int gl = tid;
        int grow = (gl >> 3) * HD + col0 + (gl & 7);
        bias_sh[gl] = dir ? (bih_b[grow] + bhh_b[grow]) : (bih_f[grow] + bhh_f[grow]);
    }
    if (tid < 64) c_sh[tid] = 0.0f;
    __syncthreads();

    int warp = tid >> 5, lane = tid & 31;
    int* myctr = &g_ctr[layer * 2 + dir];
    const float4* w4 = (const float4*)w_sm;
    const float4* h4 = (const float4*)h_sh;
    float4* part4 = (float4*)part;

    int gl_r = tid >> 3, b_r = tid & 7;     // reduce-stage role
    int grow_r = (gl_r >> 3) * HD + col0 + (gl_r & 7);

    for (int ti = 0; ti < TT; ++ti) {
        int t = dir ? (TT - 1 - ti) : ti;

        // prefetch input-projection value (independent of h)
        float gxv = __ldg(&g_gx[(size_t)(b_r * TT + t) * (2 * GG) + dir * GG + grow_r]);

        if (ti > 0) {
            if (tid == 0) {
                int target = NBD * ti;
                int v;
                do {
                    asm volatile("ld.acquire.gpu.b32 %0, [%1];" : "=r"(v) : "l"(myctr) : "memory");
                    if (v < target) __nanosleep(64);
                } while (v < target);
            }
            __syncthreads();
            const float4* src = (const float4*)(g_h + ((size_t)(ti & 1) * 2 + dir) * (BB * HD));
            float4* dst = (float4*)h_sh;
            for (int i = tid; i < (BB * HD) / 4; i += 256) dst[i] = src[i];
            __syncthreads();
        } else {
            for (int i = tid; i < BB * HD; i += 256) h_sh[i] = 0.0f;
            __syncthreads();
        }

        // partial dots: lane = gate-local row, warp covers 48 k, acc over 8 batches
        float acc0 = 0.f, acc1 = 0.f, acc2 = 0.f, acc3 = 0.f, acc4 = 0.f, acc5 = 0.f, acc6 = 0.f, acc7 = 0.f;
        int k0q = warp * 12;
#pragma unroll
        for (int kk = 0; kk < 12; kk++) {
            float4 wv = w4[(k0q + kk) * 32 + lane];
            float4 h0 = h4[0 * 96 + k0q + kk];
            float4 h1 = h4[1 * 96 + k0q + kk];
            float4 h2 = h4[2 * 96 + k0q + kk];
            float4 h3 = h4[3 * 96 + k0q + kk];
            float4 h5 = h4[4 * 96 + k0q + kk];
            float4 h6 = h4[5 * 96 + k0q + kk];
            float4 h7 = h4[6 * 96 + k0q + kk];
            float4 h8 = h4[7 * 96 + k0q + kk];
            acc0 += wv.x * h0.x + wv.y * h0.y + wv.z * h0.z + wv.w * h0.w;
            acc1 += wv.x * h1.x + wv.y * h1.y + wv.z * h1.z + wv.w * h1.w;
            acc2 += wv.x * h2.x + wv.y * h2.y + wv.z * h2.z + wv.w * h2.w;
            acc3 += wv.x * h3.x + wv.y * h3.y + wv.z * h3.z + wv.w * h3.w;
            acc4 += wv.x * h5.x + wv.y * h5.y + wv.z * h5.z + wv.w * h5.w;
            acc5 += wv.x * h6.x + wv.y * h6.y + wv.z * h6.z + wv.w * h6.w;
            acc6 += wv.x * h7.x + wv.y * h7.y + wv.z * h7.z + wv.w * h7.w;
            acc7 += wv.x * h8.x + wv.y * h8.y + wv.z * h8.z + wv.w * h8.w;
        }
        part4[(warp * 32 + lane) * 2]     = make_float4(acc0, acc1, acc2, acc3);
        part4[(warp * 32 + lane) * 2 + 1] = make_float4(acc4, acc5, acc6, acc7);
        __syncthreads();

        // reduce across warps, add gx + bias
        float gsum = gxv + bias_sh[gl_r];
#pragma unroll
        for (int w = 0; w < 8; w++) gsum += part[w * 256 + tid];
        gate_sh[tid] = gsum;
        __syncthreads();

        // finalize: 64 threads own (column c, batch b)
        if (tid < 64) {
            int c = tid >> 3, b = tid & 7;
            float iv = gate_sh[(0 * 8 + c) * 8 + b];
            float fv = gate_sh[(1 * 8 + c) * 8 + b];
            float gv = gate_sh[(2 * 8 + c) * 8 + b];
            float ov = gate_sh[(3 * 8 + c) * 8 + b];
            float si = 1.0f / (1.0f + expf(-iv));
            float sf = 1.0f / (1.0f + expf(-fv));
            float so = 1.0f / (1.0f + expf(-ov));
            float cn = sf * c_sh[tid] + si * tanhf(gv);
            float hn = so * tanhf(cn);
            c_sh[tid] = cn;
            int col = col0 + c;
            g_h[((size_t)((ti + 1) & 1) * 2 + dir) * (BB * HD) + b * HD + col] = hn;
            size_t eidx = (size_t)(b * TT + t) * HH + dir * HD + col;
            g_enc[eidx]  = hn;
            g_x_bf[eidx] = __float2bfloat16_rn(hn);
        }
        __syncthreads();
        if (tid == 0) {
            __threadfence();
            atomicAdd(myctr, 1);
        }
    }
}

// ---------------- segment mean pool + MLP scorer ----------------
__global__ __launch_bounds__(256) void pool_mlp_kernel(
    const int* __restrict__ sb,
    const float* __restrict__ w1, const float* __restrict__ b1,
    const float* __restrict__ w2, const float* __restrict__ b2,
    float* __restrict__ out)
{
    __shared__ float mean_sh[HH];
    __shared__ float red[8];

    int b = blockIdx.x >> 4, s = blockIdx.x & 15;
    int tid = threadIdx.x;
    int end = sb[b * SS + s];
    int start = s ? sb[b * SS + s - 1] : 0;
    float inv = 1.0f / fmaxf((float)(end - start), 1.0f);

    float a0 = 0.f, a1 = 0.f, a2 = 0.f;
    for (int t = start; t < end; t++) {
        const float* row = g_enc + (size_t)(b * TT + t) * HH;
        a0 += row[tid]; a1 += row[tid + 256]; a2 += row[tid + 512];
    }
    mean_sh[tid] = a0 * inv; mean_sh[tid + 256] = a1 * inv; mean_sh[tid + 512] = a2 * inv;
    __syncthreads();

    int warp = tid >> 5, lane = tid & 31;
    float wpart = 0.f;
    for (int j = warp; j < HD; j += 8) {
        const float* wr = w1 + (size_t)j * HH;
        float acc = 0.f;
        for (int d = lane; d < HH; d += 32) acc += mean_sh[d] * wr[d];
#pragma unroll
        for (int o = 16; o; o >>= 1) acc += __shfl_xor_sync(0xFFFFFFFFu, acc, o);
        if (lane == 0) {
            float h = fmaxf(acc + b1[j], 0.0f);
            wpart += h * w2[j];
        }
    }
    if (lane == 0) red[warp] = wpart;
    __syncthreads();
    if (tid == 0) {
        float h2 = b2[0];
#pragma unroll
        for (int w = 0; w < 8; w++) h2 += red[w];
        out[b * SS + s] = 1.0f / (1.0f + expf(-h2));
    }
}

__global__ void min_kernel(float* __restrict__ out) {
    int b = threadIdx.x;
    if (b < BB) {
        float m = 1e30f;
        for (int s = 0; s < SS; s++) {
            float r = out[b * SS + s];
            float mask = (r > 0.0f) ? 1.0f : 0.0f;
            float v = r * mask + (1.0f - mask);
            m = fminf(m, v);
        }
        out[BB * SS + b] = m;
    }
}

// ---------------- launch ----------------
extern "C" void kernel_launch(void* const* d_in, const int* in_sizes, int n_in,
                              void* d_out, int out_size) {
    const int*   ids = (const int*)d_in[0];
    const int*   sb  = (const int*)d_in[1];
    const float* emb = (const float*)d_in[2];
    // layer 0: 3..10, layer 1: 11..18
    const float* w_ih_l0f = (const float*)d_in[3];
    const float* w_hh_l0f = (const float*)d_in[4];
    const float* b_ih_l0f = (const float*)d_in[5];
    const float* b_hh_l0f = (const float*)d_in[6];
    const float* w_ih_l0b = (const float*)d_in[7];
    const float* w_hh_l0b = (const float*)d_in[8];
    const float* b_ih_l0b = (const float*)d_in[9];
    const float* b_hh_l0b = (const float*)d_in[10];
    const float* w_ih_l1f = (const float*)d_in[11];
    const float* w_hh_l1f = (const float*)d_in[12];
    const float* b_ih_l1f = (const float*)d_in[13];
    const float* b_hh_l1f = (const float*)d_in[14];
    const float* w_ih_l1b = (const float*)d_in[15];
    const float* w_hh_l1b = (const float*)d_in[16];
    const float* b_ih_l1b = (const float*)d_in[17];
    const float* b_hh_l1b = (const float*)d_in[18];
    const float* w1 = (const float*)d_in[19];
    const float* b1 = (const float*)d_in[20];
    const float* w2 = (const float*)d_in[21];
    const float* b2 = (const float*)d_in[22];
    float* out = (float*)d_out;

    cudaFuncSetAttribute((const void*)recur_kernel,
                         cudaFuncAttributeMaxDynamicSharedMemorySize, RSMEM_BYTES);

    init_ctr_kernel<<<1, 32>>>();
    emb_kernel<<<BB * TT, 256>>>(ids, emb);

    int nconv = 2 * GG * HH;
    conv_w_kernel<<<(nconv + 255) / 256, 256>>>(w_ih_l0f, w_ih_l0b, 0);
    conv_w_kernel<<<(nconv + 255) / 256, 256>>>(w_ih_l1f, w_ih_l1b, 1);

    dim3 ggrid(2 * GG / 128, BB * TT / 64);   // (24, 128)

    // layer 0
    {
        __nv_bfloat16* wptr = nullptr;
        cudaGetSymbolAddress((void**)&wptr, g_wbf);
        gemm_bf16_kernel<<<ggrid, 256>>>(wptr);
        recur_kernel<<<2 * NBD, 256, RSMEM_BYTES>>>(0, w_hh_l0f, w_hh_l0b,
                                                    b_ih_l0f, b_hh_l0f, b_ih_l0b, b_hh_l0b);
    }
    // layer 1
    {
        __nv_bfloat16* wptr = nullptr;
        cudaGetSymbolAddress((void**)&wptr, g_wbf);
        gemm_bf16_kernel<<<ggrid, 256>>>(wptr + (size_t)2 * GG * HH);
        recur_kernel<<<2 * NBD, 256, RSMEM_BYTES>>>(1, w_hh_l1f, w_hh_l1b,
                                                    b_ih_l1f, b_hh_l1f, b_ih_l1b, b_hh_l1b);
    }

    pool_mlp_kernel<<<BB * SS, 256>>>(sb, w1, b1, w2, b2, out);
    if (out_size >= BB * SS + BB)
        min_kernel<<<1, 32>>>(out);
}